// round 4
// baseline (speedup 1.0000x reference)
#include <cuda_runtime.h>
#include <cuda_bf16.h>

#define IN_CH 256
#define OUT_CH 128
#define MAX_NODES 100000

// Scratch: __device__ globals (no allocation allowed in kernel_launch)
__device__ float g_h[MAX_NODES * OUT_CH];     // x @ W
__device__ float g_agg[MAX_NODES * OUT_CH];   // edge aggregation
__device__ float g_dinv[MAX_NODES];           // deg^-1/2
__device__ int   g_deg[MAX_NODES];            // degree incl. self-loop

// ---------------------------------------------------------------------------
// K0: zero agg, init deg=1 (self-loop)
// ---------------------------------------------------------------------------
__global__ void init_kernel(int n) {
    int i = blockIdx.x * blockDim.x + threadIdx.x;
    int total = n * OUT_CH;
    if (i < total) g_agg[i] = 0.0f;
    if (i < n) g_deg[i] = 1;
}

// ---------------------------------------------------------------------------
// K1: degree count over edge destinations (edge_index is int32!)
// ---------------------------------------------------------------------------
__global__ void deg_kernel(const int* __restrict__ ei, int nE) {
    int e = blockIdx.x * blockDim.x + threadIdx.x;
    if (e < nE) {
        int d = ei[nE + e];   // col (destination)
        atomicAdd(&g_deg[d], 1);
    }
}

// ---------------------------------------------------------------------------
// K2: dinv = rsqrt(deg)   (deg >= 1 always due to self-loops)
// ---------------------------------------------------------------------------
__global__ void dinv_kernel(int n) {
    int i = blockIdx.x * blockDim.x + threadIdx.x;
    if (i < n) g_dinv[i] = rsqrtf((float)g_deg[i]);
}

// ---------------------------------------------------------------------------
// K3: h = x @ W  (SIMT smem-tiled; 8 rows x 128 cols per 128-thread block)
// ---------------------------------------------------------------------------
#define GEMM_ROWS 8
#define GEMM_KC   64
__global__ void gemm_kernel(const float* __restrict__ x,
                            const float* __restrict__ W, int n) {
    __shared__ float Ws[GEMM_KC * OUT_CH];       // 32 KB
    __shared__ float xs[GEMM_ROWS][GEMM_KC];     // 2 KB
    int c  = threadIdx.x;                        // 0..127 (output channel)
    int r0 = blockIdx.x * GEMM_ROWS;
    float acc[GEMM_ROWS];
#pragma unroll
    for (int r = 0; r < GEMM_ROWS; ++r) acc[r] = 0.0f;

    for (int k0 = 0; k0 < IN_CH; k0 += GEMM_KC) {
        // stage W chunk: KC*128 floats, 64 per thread (coalesced)
        for (int i = c; i < GEMM_KC * OUT_CH; i += OUT_CH)
            Ws[i] = W[(k0 + (i >> 7)) * OUT_CH + (i & 127)];
        // stage x tile: 8 rows x KC
        for (int i = c; i < GEMM_ROWS * GEMM_KC; i += OUT_CH) {
            int rr = i / GEMM_KC, kk = i % GEMM_KC;
            xs[rr][kk] = (r0 + rr < n) ? x[(r0 + rr) * IN_CH + k0 + kk] : 0.0f;
        }
        __syncthreads();
#pragma unroll
        for (int k = 0; k < GEMM_KC; ++k) {
            float w = Ws[k * OUT_CH + c];
#pragma unroll
            for (int r = 0; r < GEMM_ROWS; ++r)
                acc[r] = fmaf(xs[r][k], w, acc[r]);
        }
        __syncthreads();
    }
#pragma unroll
    for (int r = 0; r < GEMM_ROWS; ++r)
        if (r0 + r < n) g_h[(r0 + r) * OUT_CH + c] = acc[r];
}

// ---------------------------------------------------------------------------
// K4: edge scatter  agg[col] += h[row] * dinv[row]*dinv[col]
//     2 edges per 256-thread block; 1 thread per (edge, channel)
// ---------------------------------------------------------------------------
__global__ void scatter_kernel(const int* __restrict__ ei, int nE) {
    int e = blockIdx.x * 2 + (threadIdx.x >> 7);
    int c = threadIdx.x & 127;
    if (e >= nE) return;
    int r = ei[e];        // row (source)
    int d = ei[nE + e];   // col (destination)
    float w = g_dinv[r] * g_dinv[d];
    atomicAdd(&g_agg[d * OUT_CH + c], g_h[r * OUT_CH + c] * w);
}

// ---------------------------------------------------------------------------
// K5: finalize: + self-loop + bias, min-max scale, L2 normalize
//     one 128-thread block per node
// ---------------------------------------------------------------------------
__global__ void finalize_kernel(const float* __restrict__ b,
                                float* __restrict__ out, int n) {
    int i = blockIdx.x;
    int c = threadIdx.x;         // 0..127
    float di = g_dinv[i];
    float v = g_agg[i * OUT_CH + c] + g_h[i * OUT_CH + c] * (di * di) + b[c];

    // --- block min/max over 128 values ---
    float mn = v, mx = v;
#pragma unroll
    for (int o = 16; o; o >>= 1) {
        mn = fminf(mn, __shfl_xor_sync(0xffffffffu, mn, o));
        mx = fmaxf(mx, __shfl_xor_sync(0xffffffffu, mx, o));
    }
    __shared__ float smn[4], smx[4], ssum[4];
    int w = c >> 5, l = c & 31;
    if (l == 0) { smn[w] = mn; smx[w] = mx; }
    __syncthreads();
    mn = fminf(fminf(smn[0], smn[1]), fminf(smn[2], smn[3]));
    mx = fmaxf(fmaxf(smx[0], smx[1]), fmaxf(smx[2], smx[3]));

    float z = (v - mn) / (mx - mn);

    // --- block sum of z^2 ---
    float s = z * z;
#pragma unroll
    for (int o = 16; o; o >>= 1) s += __shfl_xor_sync(0xffffffffu, s, o);
    if (l == 0) ssum[w] = s;
    __syncthreads();
    float tot = ssum[0] + ssum[1] + ssum[2] + ssum[3];
    float nrm = fmaxf(sqrtf(tot), 1e-12f);
    out[i * OUT_CH + c] = z / nrm;
}

// ---------------------------------------------------------------------------
extern "C" void kernel_launch(void* const* d_in, const int* in_sizes, int n_in,
                              void* d_out, int out_size) {
    const float* x  = (const float*)d_in[0];
    const int*   ei = (const int*)d_in[1];     // int32! (JAX x64 disabled)
    const float* W  = (const float*)d_in[2];
    const float* b  = (const float*)d_in[3];
    float*       out = (float*)d_out;

    int n  = in_sizes[0] / IN_CH;   // 100000
    int nE = in_sizes[1] / 2;       // 1600000

    init_kernel<<<(n * OUT_CH + 255) / 256, 256>>>(n);
    deg_kernel<<<(nE + 255) / 256, 256>>>(ei, nE);
    dinv_kernel<<<(n + 255) / 256, 256>>>(n);
    gemm_kernel<<<(n + GEMM_ROWS - 1) / GEMM_ROWS, OUT_CH>>>(x, W, n);
    scatter_kernel<<<(nE + 1) / 2, 256>>>(ei, nE);
    finalize_kernel<<<n, OUT_CH>>>(b, out, n);
}

// round 5
// speedup vs baseline: 2.8959x; 2.8959x over previous
#include <cuda_runtime.h>
#include <cuda_bf16.h>

#define IN_CH 256
#define OUT_CH 128
#define MAX_NODES 100000

__device__ float g_h[MAX_NODES * OUT_CH];     // x @ W
__device__ float g_agg[MAX_NODES * OUT_CH];   // edge aggregation
__device__ float g_dinv[MAX_NODES];           // deg^-1/2
__device__ int   g_deg[MAX_NODES];            // degree incl. self-loop

// ---------------------------------------------------------------------------
// K0: zero agg, init deg=1 (self-loop)
// ---------------------------------------------------------------------------
__global__ void init_kernel(int n) {
    int i = blockIdx.x * blockDim.x + threadIdx.x;
    if (i < n * (OUT_CH / 4)) ((float4*)g_agg)[i] = make_float4(0.f, 0.f, 0.f, 0.f);
    if (i < n) g_deg[i] = 1;
}

// ---------------------------------------------------------------------------
// K1: degree count over destinations (edge_index is int32)
// ---------------------------------------------------------------------------
__global__ void deg_kernel(const int* __restrict__ ei, int nE) {
    int e = blockIdx.x * blockDim.x + threadIdx.x;
    if (e < nE) atomicAdd(&g_deg[ei[nE + e]], 1);
}

// ---------------------------------------------------------------------------
// K2: dinv = rsqrt(deg)
// ---------------------------------------------------------------------------
__global__ void dinv_kernel(int n) {
    int i = blockIdx.x * blockDim.x + threadIdx.x;
    if (i < n) g_dinv[i] = rsqrtf((float)g_deg[i]);
}

// ---------------------------------------------------------------------------
// K3: h = x @ W  — register-blocked: 256 thr, 64x128 tile, 8x4 per thread
// ---------------------------------------------------------------------------
#define BM 64
#define KC 16
__global__ __launch_bounds__(256) void gemm_kernel(const float* __restrict__ x,
                                                   const float* __restrict__ W, int n) {
    __shared__ float  xs[KC][BM + 4];   // k-major, padded (row stride 68: 16B aligned)
    __shared__ float4 Ws[KC][OUT_CH / 4];

    int tid = threadIdx.x;
    int tx = tid & 31;          // col group: cols tx*4 .. tx*4+3
    int ty = tid >> 5;          // row group: rows ty*8 .. ty*8+7
    int r0 = blockIdx.x * BM;

    float4 acc[8];
#pragma unroll
    for (int r = 0; r < 8; ++r) acc[r] = make_float4(0.f, 0.f, 0.f, 0.f);

    int srow = tid >> 2;        // 0..63 : x-staging row
    int skq  = tid & 3;         // 0..3  : which float4 of the KC=16 chunk

    for (int k0 = 0; k0 < IN_CH; k0 += KC) {
        // stage x tile (64 rows x 16 k), transposed to k-major
        float4 xv = make_float4(0.f, 0.f, 0.f, 0.f);
        if (r0 + srow < n)
            xv = *(const float4*)&x[(size_t)(r0 + srow) * IN_CH + k0 + skq * 4];
        xs[skq * 4 + 0][srow] = xv.x;
        xs[skq * 4 + 1][srow] = xv.y;
        xs[skq * 4 + 2][srow] = xv.z;
        xs[skq * 4 + 3][srow] = xv.w;
        // stage W tile (16 k x 128 cols), 2 float4 per thread
#pragma unroll
        for (int i = tid; i < KC * (OUT_CH / 4); i += 256) {
            int kk = i >> 5, c4 = i & 31;
            Ws[kk][c4] = *(const float4*)&W[(size_t)(k0 + kk) * OUT_CH + c4 * 4];
        }
        __syncthreads();
#pragma unroll
        for (int k = 0; k < KC; ++k) {
            float4 wv = Ws[k][tx];                       // conflict-free
            float4 xa = *(float4*)&xs[k][ty * 8];        // broadcast
            float4 xb = *(float4*)&xs[k][ty * 8 + 4];    // broadcast
            float xr[8] = {xa.x, xa.y, xa.z, xa.w, xb.x, xb.y, xb.z, xb.w};
#pragma unroll
            for (int r = 0; r < 8; ++r) {
                acc[r].x = fmaf(xr[r], wv.x, acc[r].x);
                acc[r].y = fmaf(xr[r], wv.y, acc[r].y);
                acc[r].z = fmaf(xr[r], wv.z, acc[r].z);
                acc[r].w = fmaf(xr[r], wv.w, acc[r].w);
            }
        }
        __syncthreads();
    }
#pragma unroll
    for (int r = 0; r < 8; ++r) {
        int row = r0 + ty * 8 + r;
        if (row < n)
            *(float4*)&g_h[(size_t)row * OUT_CH + tx * 4] = acc[r];
    }
}

// ---------------------------------------------------------------------------
// K4: edge scatter — one warp per edge, float4 vector reductions
// ---------------------------------------------------------------------------
__global__ __launch_bounds__(256) void scatter_kernel(const int* __restrict__ ei, int nE) {
    int warp = (blockIdx.x * blockDim.x + threadIdx.x) >> 5;
    int lane = threadIdx.x & 31;
    if (warp >= nE) return;
    int r = ei[warp];            // source (broadcast load)
    int d = ei[nE + warp];       // destination (broadcast load)
    float w = g_dinv[r] * g_dinv[d];
    float4 hv = *(const float4*)&g_h[(size_t)r * OUT_CH + lane * 4];
    float* dst = &g_agg[(size_t)d * OUT_CH + lane * 4];
    asm volatile("red.global.add.v4.f32 [%0], {%1, %2, %3, %4};"
                 :: "l"(dst), "f"(hv.x * w), "f"(hv.y * w), "f"(hv.z * w), "f"(hv.w * w)
                 : "memory");
}

// ---------------------------------------------------------------------------
// K5: finalize — + self-loop + bias, min-max scale, L2 normalize
// ---------------------------------------------------------------------------
__global__ void finalize_kernel(const float* __restrict__ b,
                                float* __restrict__ out, int n) {
    int i = blockIdx.x;
    int c = threadIdx.x;         // 0..127
    float di = g_dinv[i];
    float v = g_agg[i * OUT_CH + c] + g_h[i * OUT_CH + c] * (di * di) + b[c];

    float mn = v, mx = v;
#pragma unroll
    for (int o = 16; o; o >>= 1) {
        mn = fminf(mn, __shfl_xor_sync(0xffffffffu, mn, o));
        mx = fmaxf(mx, __shfl_xor_sync(0xffffffffu, mx, o));
    }
    __shared__ float smn[4], smx[4], ssum[4];
    int w = c >> 5, l = c & 31;
    if (l == 0) { smn[w] = mn; smx[w] = mx; }
    __syncthreads();
    mn = fminf(fminf(smn[0], smn[1]), fminf(smn[2], smn[3]));
    mx = fmaxf(fmaxf(smx[0], smx[1]), fmaxf(smx[2], smx[3]));

    float z = (v - mn) / (mx - mn);

    float s = z * z;
#pragma unroll
    for (int o = 16; o; o >>= 1) s += __shfl_xor_sync(0xffffffffu, s, o);
    if (l == 0) ssum[w] = s;
    __syncthreads();
    float tot = ssum[0] + ssum[1] + ssum[2] + ssum[3];
    float nrm = fmaxf(sqrtf(tot), 1e-12f);
    out[i * OUT_CH + c] = z / nrm;
}

// ---------------------------------------------------------------------------
extern "C" void kernel_launch(void* const* d_in, const int* in_sizes, int n_in,
                              void* d_out, int out_size) {
    const float* x  = (const float*)d_in[0];
    const int*   ei = (const int*)d_in[1];     // int32
    const float* W  = (const float*)d_in[2];
    const float* b  = (const float*)d_in[3];
    float*       out = (float*)d_out;

    int n  = in_sizes[0] / IN_CH;   // 100000
    int nE = in_sizes[1] / 2;       // 1600000

    init_kernel<<<(n * (OUT_CH / 4) + 255) / 256, 256>>>(n);
    deg_kernel<<<(nE + 255) / 256, 256>>>(ei, nE);
    dinv_kernel<<<(n + 255) / 256, 256>>>(n);
    gemm_kernel<<<(n + BM - 1) / BM, 256>>>(x, W, n);
    scatter_kernel<<<(nE * 32 + 255) / 256, 256>>>(ei, nE);
    finalize_kernel<<<n, OUT_CH>>>(b, out, n);
}

// round 6
// speedup vs baseline: 4.7220x; 1.6306x over previous
#include <cuda_runtime.h>
#include <cuda_bf16.h>

#define IN_CH 256
#define OUT_CH 128
#define MAX_NODES 100000
#define MAX_EDGES 1600000
#define SCAN_B 1024

__device__ float g_h[MAX_NODES * OUT_CH];   // x @ W
__device__ float g_dinv[MAX_NODES];         // (deg incl self)^-1/2
__device__ int   g_cnt[MAX_NODES];          // in-degree (excl self)
__device__ int   g_off[MAX_NODES];          // CSR row offsets (exclusive scan of cnt)
__device__ int   g_cur[MAX_NODES];          // fill cursors
__device__ int   g_esrc[MAX_EDGES];         // edge sources, grouped by destination
__device__ int   g_bsum[128];               // scan partials
__device__ int   g_bbase[128];

// ---------------------------------------------------------------------------
__global__ void zero_kernel(int n) {
    int i = blockIdx.x * blockDim.x + threadIdx.x;
    if (i < n) g_cnt[i] = 0;
}

__global__ void deg_kernel(const int* __restrict__ ei, int nE) {
    int e = blockIdx.x * blockDim.x + threadIdx.x;
    if (e < nE) atomicAdd(&g_cnt[ei[nE + e]], 1);
}

__global__ void dinv_kernel(int n) {
    int i = blockIdx.x * blockDim.x + threadIdx.x;
    if (i < n) g_dinv[i] = rsqrtf((float)(g_cnt[i] + 1));   // +1 self-loop
}

// --- scan: exclusive prefix over g_cnt -> g_off -------------------------------
__global__ void scanA_kernel(int n) {
    __shared__ int s[SCAN_B];
    int i = blockIdx.x * SCAN_B + threadIdx.x;
    int v = (i < n) ? g_cnt[i] : 0;
    s[threadIdx.x] = v;
    __syncthreads();
    for (int o = 1; o < SCAN_B; o <<= 1) {
        int t = (threadIdx.x >= o) ? s[threadIdx.x - o] : 0;
        __syncthreads();
        s[threadIdx.x] += t;
        __syncthreads();
    }
    if (i < n) g_off[i] = s[threadIdx.x] - v;   // exclusive within block
    if (threadIdx.x == SCAN_B - 1) g_bsum[blockIdx.x] = s[SCAN_B - 1];
}

__global__ void scanB_kernel(int nb) {
    __shared__ int s[128];
    int t = threadIdx.x;
    int v = (t < nb) ? g_bsum[t] : 0;
    s[t] = v;
    __syncthreads();
    for (int o = 1; o < 128; o <<= 1) {
        int u = (t >= o) ? s[t - o] : 0;
        __syncthreads();
        s[t] += u;
        __syncthreads();
    }
    if (t < nb) g_bbase[t] = s[t] - v;
}

__global__ void scanC_kernel(int n) {
    int i = blockIdx.x * blockDim.x + threadIdx.x;
    if (i < n) {
        int o = g_off[i] + g_bbase[i / SCAN_B];
        g_off[i] = o;
        g_cur[i] = o;
    }
}

// --- CSR fill ----------------------------------------------------------------
__global__ void fill_kernel(const int* __restrict__ ei, int nE) {
    int e = blockIdx.x * blockDim.x + threadIdx.x;
    if (e < nE) {
        int d = ei[nE + e];
        int slot = atomicAdd(&g_cur[d], 1);
        g_esrc[slot] = ei[e];
    }
}

// ---------------------------------------------------------------------------
// GEMM: h = x @ W — 128x128 tile, 256 thr, 8x8 per thread
// ---------------------------------------------------------------------------
#define BM 128
#define KC 16
__global__ __launch_bounds__(256) void gemm_kernel(const float* __restrict__ x,
                                                   const float* __restrict__ W, int n) {
    __shared__ float  xs[KC][BM + 4];        // k-major; stride 132*4=528B (16B mult)
    __shared__ float4 Ws[KC][OUT_CH / 4];    // 32 float4 per k

    int tid = threadIdx.x;
    int tx = tid & 15;          // cols: tx*4..+3 and 64+tx*4..+3
    int ty = tid >> 4;          // rows: ty*8..+7
    int r0 = blockIdx.x * BM;

    float4 acc0[8], acc1[8];
#pragma unroll
    for (int r = 0; r < 8; ++r) {
        acc0[r] = make_float4(0.f, 0.f, 0.f, 0.f);
        acc1[r] = make_float4(0.f, 0.f, 0.f, 0.f);
    }

    for (int k0 = 0; k0 < IN_CH; k0 += KC) {
        // stage x tile (128 rows x 16 k), transposed: 2 float4 per thread
#pragma unroll
        for (int j = 0; j < 2; ++j) {
            int item = tid + 256 * j;           // 0..511
            int row = item >> 2, quad = item & 3;
            float4 xv = make_float4(0.f, 0.f, 0.f, 0.f);
            if (r0 + row < n)
                xv = *(const float4*)&x[(size_t)(r0 + row) * IN_CH + k0 + quad * 4];
            xs[quad * 4 + 0][row] = xv.x;
            xs[quad * 4 + 1][row] = xv.y;
            xs[quad * 4 + 2][row] = xv.z;
            xs[quad * 4 + 3][row] = xv.w;
        }
        // stage W tile (16 k x 128 cols): 2 float4 per thread
#pragma unroll
        for (int j = 0; j < 2; ++j) {
            int item = tid + 256 * j;           // 0..511
            int kk = item >> 5, c4 = item & 31;
            Ws[kk][c4] = *(const float4*)&W[(size_t)(k0 + kk) * OUT_CH + c4 * 4];
        }
        __syncthreads();
#pragma unroll
        for (int k = 0; k < KC; ++k) {
            float4 w0 = Ws[k][tx];          // conflict-free across 16 tx
            float4 w1 = Ws[k][tx + 16];
            float4 xa = *(float4*)&xs[k][ty * 8];      // broadcast
            float4 xb = *(float4*)&xs[k][ty * 8 + 4];  // broadcast
            float xr[8] = {xa.x, xa.y, xa.z, xa.w, xb.x, xb.y, xb.z, xb.w};
#pragma unroll
            for (int r = 0; r < 8; ++r) {
                acc0[r].x = fmaf(xr[r], w0.x, acc0[r].x);
                acc0[r].y = fmaf(xr[r], w0.y, acc0[r].y);
                acc0[r].z = fmaf(xr[r], w0.z, acc0[r].z);
                acc0[r].w = fmaf(xr[r], w0.w, acc0[r].w);
                acc1[r].x = fmaf(xr[r], w1.x, acc1[r].x);
                acc1[r].y = fmaf(xr[r], w1.y, acc1[r].y);
                acc1[r].z = fmaf(xr[r], w1.z, acc1[r].z);
                acc1[r].w = fmaf(xr[r], w1.w, acc1[r].w);
            }
        }
        __syncthreads();
    }
#pragma unroll
    for (int r = 0; r < 8; ++r) {
        int row = r0 + ty * 8 + r;
        if (row < n) {
            *(float4*)&g_h[(size_t)row * OUT_CH + tx * 4] = acc0[r];
            *(float4*)&g_h[(size_t)row * OUT_CH + 64 + tx * 4] = acc1[r];
        }
    }
}

// ---------------------------------------------------------------------------
// Gather + finalize: one warp per node. acc starts with self-loop + bias,
// accumulates in-edges from CSR, then fused min-max scale + L2 normalize.
// ---------------------------------------------------------------------------
__global__ __launch_bounds__(256) void gather_kernel(const float* __restrict__ b,
                                                     float* __restrict__ out, int n) {
    int node = (blockIdx.x * blockDim.x + threadIdx.x) >> 5;
    int lane = threadIdx.x & 31;
    if (node >= n) return;

    float di = g_dinv[node];
    float4 hv = *(const float4*)&g_h[(size_t)node * OUT_CH + lane * 4];
    float4 bv = *(const float4*)&b[lane * 4];
    float s2 = di * di;
    float4 acc = make_float4(fmaf(hv.x, s2, bv.x), fmaf(hv.y, s2, bv.y),
                             fmaf(hv.z, s2, bv.z), fmaf(hv.w, s2, bv.w));

    int base = g_off[node];
    int cnt  = g_cnt[node];
    for (int j = 0; j < cnt; ++j) {
        int src = g_esrc[base + j];            // broadcast
        float w = g_dinv[src] * di;            // broadcast
        float4 sv = *(const float4*)&g_h[(size_t)src * OUT_CH + lane * 4];
        acc.x = fmaf(sv.x, w, acc.x);
        acc.y = fmaf(sv.y, w, acc.y);
        acc.z = fmaf(sv.z, w, acc.z);
        acc.w = fmaf(sv.w, w, acc.w);
    }

    // warp min/max over all 128 channels
    float mn = fminf(fminf(acc.x, acc.y), fminf(acc.z, acc.w));
    float mx = fmaxf(fmaxf(acc.x, acc.y), fmaxf(acc.z, acc.w));
#pragma unroll
    for (int o = 16; o; o >>= 1) {
        mn = fminf(mn, __shfl_xor_sync(0xffffffffu, mn, o));
        mx = fmaxf(mx, __shfl_xor_sync(0xffffffffu, mx, o));
    }
    float inv = 1.0f / (mx - mn);
    float4 z = make_float4((acc.x - mn) * inv, (acc.y - mn) * inv,
                           (acc.z - mn) * inv, (acc.w - mn) * inv);
    float ss = z.x * z.x + z.y * z.y + z.z * z.z + z.w * z.w;
#pragma unroll
    for (int o = 16; o; o >>= 1) ss += __shfl_xor_sync(0xffffffffu, ss, o);
    float rn = 1.0f / fmaxf(sqrtf(ss), 1e-12f);
    z.x *= rn; z.y *= rn; z.z *= rn; z.w *= rn;
    *(float4*)&out[(size_t)node * OUT_CH + lane * 4] = z;
}

// ---------------------------------------------------------------------------
extern "C" void kernel_launch(void* const* d_in, const int* in_sizes, int n_in,
                              void* d_out, int out_size) {
    const float* x  = (const float*)d_in[0];
    const int*   ei = (const int*)d_in[1];     // int32
    const float* W  = (const float*)d_in[2];
    const float* b  = (const float*)d_in[3];
    float*       out = (float*)d_out;

    int n  = in_sizes[0] / IN_CH;   // 100000
    int nE = in_sizes[1] / 2;       // 1600000
    int nb = (n + SCAN_B - 1) / SCAN_B;

    zero_kernel<<<(n + 255) / 256, 256>>>(n);
    deg_kernel<<<(nE + 255) / 256, 256>>>(ei, nE);
    dinv_kernel<<<(n + 255) / 256, 256>>>(n);
    scanA_kernel<<<nb, SCAN_B>>>(n);
    scanB_kernel<<<1, 128>>>(nb);
    scanC_kernel<<<(n + 255) / 256, 256>>>(n);
    fill_kernel<<<(nE + 255) / 256, 256>>>(ei, nE);
    gemm_kernel<<<(n + BM - 1) / BM, 256>>>(x, W, n);
    gather_kernel<<<(n * 32 + 255) / 256, 256>>>(b, out, n);
}

// round 10
// speedup vs baseline: 6.8294x; 1.4463x over previous
#include <cuda_runtime.h>
#include <cuda_bf16.h>
#include <cstdint>

#define IN_CH 256
#define OUT_CH 128
#define MAX_NODES 100000
#define MAX_EDGES 1600000
#define SCAN_B 1024

__device__ float g_h[MAX_NODES * OUT_CH];   // x @ W
__device__ float g_dinv[MAX_NODES];         // (deg incl self)^-1/2
__device__ int   g_cnt[MAX_NODES];          // in-degree (excl self)
__device__ int   g_off[MAX_NODES];          // CSR row offsets
__device__ int   g_cur[MAX_NODES];          // fill cursors
__device__ int   g_esrc[MAX_EDGES];         // edge sources grouped by dest
__device__ int   g_bsum[128];
__device__ int   g_bbase[128];

// ===================== small pipeline kernels =====================
__global__ void zero_kernel(int n) {
    int i = blockIdx.x * blockDim.x + threadIdx.x;
    if (i < n) g_cnt[i] = 0;
}
__global__ void deg_kernel(const int* __restrict__ ei, int nE) {
    int e = blockIdx.x * blockDim.x + threadIdx.x;
    if (e < nE) atomicAdd(&g_cnt[ei[nE + e]], 1);
}
__global__ void dinv_kernel(int n) {
    int i = blockIdx.x * blockDim.x + threadIdx.x;
    if (i < n) g_dinv[i] = rsqrtf((float)(g_cnt[i] + 1));
}
__global__ void scanA_kernel(int n) {
    __shared__ int s[SCAN_B];
    int i = blockIdx.x * SCAN_B + threadIdx.x;
    int v = (i < n) ? g_cnt[i] : 0;
    s[threadIdx.x] = v;
    __syncthreads();
    for (int o = 1; o < SCAN_B; o <<= 1) {
        int t = (threadIdx.x >= o) ? s[threadIdx.x - o] : 0;
        __syncthreads();
        s[threadIdx.x] += t;
        __syncthreads();
    }
    if (i < n) g_off[i] = s[threadIdx.x] - v;
    if (threadIdx.x == SCAN_B - 1) g_bsum[blockIdx.x] = s[SCAN_B - 1];
}
__global__ void scanB_kernel(int nb) {
    __shared__ int s[128];
    int t = threadIdx.x;
    int v = (t < nb) ? g_bsum[t] : 0;
    s[t] = v;
    __syncthreads();
    for (int o = 1; o < 128; o <<= 1) {
        int u = (t >= o) ? s[t - o] : 0;
        __syncthreads();
        s[t] += u;
        __syncthreads();
    }
    if (t < nb) g_bbase[t] = s[t] - v;
}
__global__ void scanC_kernel(int n) {
    int i = blockIdx.x * blockDim.x + threadIdx.x;
    if (i < n) {
        int o = g_off[i] + g_bbase[i / SCAN_B];
        g_off[i] = o;
        g_cur[i] = o;
    }
}
__global__ void fill_kernel(const int* __restrict__ ei, int nE) {
    int e = blockIdx.x * blockDim.x + threadIdx.x;
    if (e < nE) {
        int d = ei[nE + e];
        g_esrc[atomicAdd(&g_cur[d], 1)] = ei[e];
    }
}

// ===================== tf32 mma.sync GEMM: h = x @ W =====================
// CTA: 128x128 tile, K=256 in 8 chunks of 32. 8 warps (4x2): warp tile 32x64.
// mma.sync.aligned.m16n8k8.row.col.f32.tf32.tf32.f32 (portable, sm_80+)
#define KC 32
#define A_STR 36     // words; bank = 4*(lane>>2)+(lane&3) -> conflict-free
#define B_STR 136    // words; bank = 8*(lane&3)+(lane>>2) -> conflict-free
#define EPI_STR 68   // words; 272B rows, 16B-aligned float4

__device__ __forceinline__ uint32_t f2tf(float f) {
    uint32_t u;
    asm("cvt.rna.tf32.f32 %0, %1;" : "=r"(u) : "f"(f));
    return u;
}

__global__ __launch_bounds__(256) void gemm_mma_kernel(const float* __restrict__ x,
                                                       const float* __restrict__ W, int n) {
    // union: staging A (128x36 @0) + B (32x136 @4608) = 8960 words; epi 128x68 = 8704
    __shared__ __align__(16) uint32_t sbuf[8960];   // 35840 B
    uint32_t* As = sbuf;
    uint32_t* Bs = sbuf + 128 * A_STR;

    int tid = threadIdx.x;
    int wid = tid >> 5;
    int lane = tid & 31;
    int wm = wid & 3;           // warp row: rows wm*32 .. +31
    int wn = wid >> 2;          // warp col: cols wn*64 .. +63
    int r0 = blockIdx.x * 128;

    float acc[2][8][4];
#pragma unroll
    for (int mt = 0; mt < 2; ++mt)
#pragma unroll
        for (int nt = 0; nt < 8; ++nt)
#pragma unroll
            for (int q = 0; q < 4; ++q) acc[mt][nt][q] = 0.0f;

    int lq = lane >> 2;   // 0..7  (groupID)
    int lr = lane & 3;    // 0..3  (threadID_in_group)

    for (int chunk = 0; chunk < 8; ++chunk) {
        int k0 = chunk * KC;
        // stage A: 128 rows x 32 k = 1024 float4 items (FIX: was 512)
#pragma unroll
        for (int j = 0; j < 4; ++j) {
            int item = tid + 256 * j;           // 0..1023
            int row = item >> 3, quad = item & 7;
            float4 xv = make_float4(0.f, 0.f, 0.f, 0.f);
            if (r0 + row < n)
                xv = *(const float4*)&x[(size_t)(r0 + row) * IN_CH + k0 + quad * 4];
            uint4 t = make_uint4(f2tf(xv.x), f2tf(xv.y), f2tf(xv.z), f2tf(xv.w));
            *(uint4*)&As[row * A_STR + quad * 4] = t;
        }
        // stage B: 32 k x 128 n from W (row-major), 1024 float4 items
#pragma unroll
        for (int j = 0; j < 4; ++j) {
            int item = tid + 256 * j;           // 0..1023
            int kk = item >> 5, n4 = item & 31;
            float4 wv = *(const float4*)&W[(size_t)(k0 + kk) * OUT_CH + n4 * 4];
            uint4 t = make_uint4(f2tf(wv.x), f2tf(wv.y), f2tf(wv.z), f2tf(wv.w));
            *(uint4*)&Bs[kk * B_STR + n4 * 4] = t;
        }
        __syncthreads();
#pragma unroll
        for (int ks = 0; ks < 4; ++ks) {
            int k8 = ks * 8;
            int kk = k8 + lr;
            uint32_t a[2][4];
#pragma unroll
            for (int mt = 0; mt < 2; ++mt) {
                int row = wm * 32 + mt * 16 + lq;
                a[mt][0] = As[row * A_STR + kk];
                a[mt][1] = As[(row + 8) * A_STR + kk];
                a[mt][2] = As[row * A_STR + kk + 4];
                a[mt][3] = As[(row + 8) * A_STR + kk + 4];
            }
            uint32_t bf[8][2];
#pragma unroll
            for (int nt = 0; nt < 8; ++nt) {
                int col = wn * 64 + nt * 8 + lq;
                bf[nt][0] = Bs[kk * B_STR + col];
                bf[nt][1] = Bs[(kk + 4) * B_STR + col];
            }
#pragma unroll
            for (int mt = 0; mt < 2; ++mt)
#pragma unroll
                for (int nt = 0; nt < 8; ++nt)
                    asm volatile(
                        "mma.sync.aligned.m16n8k8.row.col.f32.tf32.tf32.f32 "
                        "{%0,%1,%2,%3},{%4,%5,%6,%7},{%8,%9},{%0,%1,%2,%3};"
                        : "+f"(acc[mt][nt][0]), "+f"(acc[mt][nt][1]),
                          "+f"(acc[mt][nt][2]), "+f"(acc[mt][nt][3])
                        : "r"(a[mt][0]), "r"(a[mt][1]), "r"(a[mt][2]), "r"(a[mt][3]),
                          "r"(bf[nt][0]), "r"(bf[nt][1]));
        }
        __syncthreads();
    }

    // epilogue: two 64-col halves through padded smem, then coalesced float4 out
    float* s = (float*)sbuf;
    for (int h = 0; h < 2; ++h) {
        if (wn == h) {
#pragma unroll
            for (int mt = 0; mt < 2; ++mt)
#pragma unroll
                for (int nt = 0; nt < 8; ++nt) {
                    int row = wm * 32 + mt * 16 + lq;
                    int col = nt * 8 + 2 * lr;
                    s[row * EPI_STR + col]           = acc[mt][nt][0];
                    s[row * EPI_STR + col + 1]       = acc[mt][nt][1];
                    s[(row + 8) * EPI_STR + col]     = acc[mt][nt][2];
                    s[(row + 8) * EPI_STR + col + 1] = acc[mt][nt][3];
                }
        }
        __syncthreads();
#pragma unroll
        for (int j = 0; j < 8; ++j) {
            int item = tid + 256 * j;            // 0..2047
            int orow = item >> 4, c4 = item & 15;
            if (r0 + orow < n)
                *(float4*)&g_h[(size_t)(r0 + orow) * OUT_CH + h * 64 + c4 * 4] =
                    *(float4*)&s[orow * EPI_STR + c4 * 4];
        }
        __syncthreads();
    }
}

// ===================== gather + finalize (unchanged) =====================
__global__ __launch_bounds__(256) void gather_kernel(const float* __restrict__ b,
                                                     float* __restrict__ out, int n) {
    int node = (blockIdx.x * blockDim.x + threadIdx.x) >> 5;
    int lane = threadIdx.x & 31;
    if (node >= n) return;

    float di = g_dinv[node];
    float4 hv = *(const float4*)&g_h[(size_t)node * OUT_CH + lane * 4];
    float4 bv = *(const float4*)&b[lane * 4];
    float s2 = di * di;
    float4 acc = make_float4(fmaf(hv.x, s2, bv.x), fmaf(hv.y, s2, bv.y),
                             fmaf(hv.z, s2, bv.z), fmaf(hv.w, s2, bv.w));

    int base = g_off[node];
    int cnt  = g_cnt[node];
    for (int j = 0; j < cnt; ++j) {
        int src = g_esrc[base + j];
        float w = g_dinv[src] * di;
        float4 sv = *(const float4*)&g_h[(size_t)src * OUT_CH + lane * 4];
        acc.x = fmaf(sv.x, w, acc.x);
        acc.y = fmaf(sv.y, w, acc.y);
        acc.z = fmaf(sv.z, w, acc.z);
        acc.w = fmaf(sv.w, w, acc.w);
    }

    float mn = fminf(fminf(acc.x, acc.y), fminf(acc.z, acc.w));
    float mx = fmaxf(fmaxf(acc.x, acc.y), fmaxf(acc.z, acc.w));
#pragma unroll
    for (int o = 16; o; o >>= 1) {
        mn = fminf(mn, __shfl_xor_sync(0xffffffffu, mn, o));
        mx = fmaxf(mx, __shfl_xor_sync(0xffffffffu, mx, o));
    }
    float inv = 1.0f / (mx - mn);
    float4 z = make_float4((acc.x - mn) * inv, (acc.y - mn) * inv,
                           (acc.z - mn) * inv, (acc.w - mn) * inv);
    float ss = z.x * z.x + z.y * z.y + z.z * z.z + z.w * z.w;
#pragma unroll
    for (int o = 16; o; o >>= 1) ss += __shfl_xor_sync(0xffffffffu, ss, o);
    float rn = 1.0f / fmaxf(sqrtf(ss), 1e-12f);
    z.x *= rn; z.y *= rn; z.z *= rn; z.w *= rn;
    *(float4*)&out[(size_t)node * OUT_CH + lane * 4] = z;
}

// ===================== launch =====================
extern "C" void kernel_launch(void* const* d_in, const int* in_sizes, int n_in,
                              void* d_out, int out_size) {
    const float* x  = (const float*)d_in[0];
    const int*   ei = (const int*)d_in[1];     // int32
    const float* W  = (const float*)d_in[2];
    const float* b  = (const float*)d_in[3];
    float*       out = (float*)d_out;

    int n  = in_sizes[0] / IN_CH;   // 100000
    int nE = in_sizes[1] / 2;       // 1600000
    int nb = (n + SCAN_B - 1) / SCAN_B;

    zero_kernel<<<(n + 255) / 256, 256>>>(n);
    deg_kernel<<<(nE + 255) / 256, 256>>>(ei, nE);
    dinv_kernel<<<(n + 255) / 256, 256>>>(n);
    scanA_kernel<<<nb, SCAN_B>>>(n);
    scanB_kernel<<<1, 128>>>(nb);
    scanC_kernel<<<(n + 255) / 256, 256>>>(n);
    fill_kernel<<<(nE + 255) / 256, 256>>>(ei, nE);
    gemm_mma_kernel<<<(n + 127) / 128, 256>>>(x, W, n);
    gather_kernel<<<(n * 32 + 255) / 256, 256>>>(b, out, n);
}